// round 16
// baseline (speedup 1.0000x reference)
#include <cuda_runtime.h>
#include <cuda_bf16.h>
#include <cuda_fp16.h>
#include <math.h>
#include <stdint.h>

#define NB 8
#define LL 512
#define EE 768
#define HH 12
#define DD 64
#define MPOS 1023
#define NHB (NB * HH)   // 96
#define MM (NB * LL)    // 4096

// ================= scratch =================
__device__ float g_bd[(size_t)NHB * LL * 512];         // band: bd[q, q+i]
__device__ __nv_bfloat16 g_Ah[MM * EE];                // pe staging, later O staging
__device__ __nv_bfloat16 g_Al[MM * EE];
__device__ __nv_bfloat16 g_Aqh[MM * EE], g_Aql[MM * EE];
__device__ __nv_bfloat16 g_Akh[MM * EE], g_Akl[MM * EE];
__device__ __nv_bfloat16 g_Avh[MM * EE], g_Avl[MM * EE];
__device__ __nv_bfloat16 g_WqH[EE * EE], g_WqL[EE * EE];
__device__ __nv_bfloat16 g_WkH[EE * EE], g_WkL[EE * EE];
__device__ __nv_bfloat16 g_WvH[EE * EE], g_WvL[EE * EE];
__device__ __nv_bfloat16 g_WoH[EE * EE], g_WoL[EE * EE];
__device__ __nv_bfloat16 g_WpH[EE * EE], g_WpL[EE * EE];
__device__ __nv_bfloat16 g_qwh[NHB * LL * DD], g_qwl[NHB * LL * DD];
__device__ __nv_bfloat16 g_qrh[NHB * LL * DD], g_qrl[NHB * LL * DD];
__device__ __nv_bfloat16 g_khh[NHB * LL * DD], g_khl[NHB * LL * DD];
__device__ __half        g_vth[NHB * DD * LL], g_vtl[NHB * DD * LL];   // fp16 V hi/lo
__device__ __nv_bfloat16 g_Rth[HH * 1024 * DD], g_Rtl[HH * 1024 * DD];

// ================= helpers =================
__device__ __forceinline__ uint32_t smem_to_u32(const void* p) {
    uint32_t a;
    asm("{ .reg .u64 tmp; cvta.to.shared.u64 tmp, %1; cvt.u32.u64 %0, tmp; }" : "=r"(a) : "l"(p));
    return a;
}
__device__ __forceinline__ void cp16(uint32_t dst, const void* src, uint32_t sz) {
    asm volatile("cp.async.cg.shared.global [%0], [%1], 16, %2;"
                 :: "r"(dst), "l"(src), "r"(sz) : "memory");
}
__device__ __forceinline__ void mma16816(float* c, const uint32_t* a, const uint32_t* b) {
    asm volatile("mma.sync.aligned.m16n8k16.row.col.f32.bf16.bf16.f32 "
        "{%0,%1,%2,%3}, {%4,%5,%6,%7}, {%8,%9}, {%0,%1,%2,%3};"
        : "+f"(c[0]), "+f"(c[1]), "+f"(c[2]), "+f"(c[3])
        : "r"(a[0]), "r"(a[1]), "r"(a[2]), "r"(a[3]), "r"(b[0]), "r"(b[1]));
}
__device__ __forceinline__ void mma16816h(float* c, const uint32_t* a, const uint32_t* b) {
    asm volatile("mma.sync.aligned.m16n8k16.row.col.f32.f16.f16.f32 "
        "{%0,%1,%2,%3}, {%4,%5,%6,%7}, {%8,%9}, {%0,%1,%2,%3};"
        : "+f"(c[0]), "+f"(c[1]), "+f"(c[2]), "+f"(c[3])
        : "r"(a[0]), "r"(a[1]), "r"(a[2]), "r"(a[3]), "r"(b[0]), "r"(b[1]));
}
__device__ __forceinline__ void ldsm4(uint32_t* r, uint32_t addr) {
    asm volatile("ldmatrix.sync.aligned.m8n8.x4.shared.b16 {%0,%1,%2,%3}, [%4];"
        : "=r"(r[0]), "=r"(r[1]), "=r"(r[2]), "=r"(r[3]) : "r"(addr));
}
__device__ __forceinline__ void bsplit(float v, __nv_bfloat16* hi, __nv_bfloat16* lo) {
    __nv_bfloat16 h = __float2bfloat16(v);
    *hi = h;
    *lo = __float2bfloat16(v - __bfloat162float(h));
}
__device__ __forceinline__ void bsplit2_store(float a, float b,
                                              __nv_bfloat16* hip, __nv_bfloat16* lop) {
    __nv_bfloat16 ha = __float2bfloat16(a), hb = __float2bfloat16(b);
    __nv_bfloat16 la = __float2bfloat16(a - __bfloat162float(ha));
    __nv_bfloat16 lb = __float2bfloat16(b - __bfloat162float(hb));
    __nv_bfloat162 hv; hv.x = ha; hv.y = hb;
    __nv_bfloat162 lv; lv.x = la; lv.y = lb;
    *(__nv_bfloat162*)hip = hv;
    *(__nv_bfloat162*)lop = lv;
}

// ================= fused prep =================
__global__ void prepAll(const float* __restrict__ qy, const float* __restrict__ ky,
                        const float* __restrict__ vl,
                        const float* __restrict__ Wq, const float* __restrict__ Wk,
                        const float* __restrict__ Wv, const float* __restrict__ Wo,
                        const float* __restrict__ Wp) {
    const int z = blockIdx.z;
    const int t = threadIdx.x;
    if (z < 3) {
        int i = (blockIdx.x * 256 + t) * 8;
        if (i >= MM * EE) return;
        const float* src = (z == 0) ? qy : (z == 1) ? ky : vl;
        __nv_bfloat16* hi = (z == 0) ? g_Aqh : (z == 1) ? g_Akh : g_Avh;
        __nv_bfloat16* lo = (z == 0) ? g_Aql : (z == 1) ? g_Akl : g_Avl;
        float4 v0 = *(const float4*)(src + i);
        float4 v1 = *(const float4*)(src + i + 4);
        float vv[8] = {v0.x, v0.y, v0.z, v0.w, v1.x, v1.y, v1.z, v1.w};
        #pragma unroll
        for (int j = 0; j < 8; j += 2)
            bsplit2_store(vv[j], vv[j+1], &hi[i + j], &lo[i + j]);
    } else if (z == 3) {
        if (blockIdx.x == 0) {
            for (int k = t; k < HH * DD; k += 256) {
                int h = k >> 6, d = k & 63;
                size_t o = ((size_t)h * 1024 + 1023) * DD + d;
                g_Rth[o] = __float2bfloat16(0.f);
                g_Rtl[o] = __float2bfloat16(0.f);
            }
        }
        int i = (blockIdx.x * 256 + t) * 8;
        if (i >= MPOS * EE) return;
        #pragma unroll
        for (int j = 0; j < 8; j += 2) {
            int e = i + j;
            int p = e / EE, c = e % EE, m = c >> 1;
            float div = __expf((float)(2 * m) * (-9.210340371976184f / (float)EE));
            float ang = (float)p * div;
            float s, cc;
            __sincosf(ang, &s, &cc);
            bsplit(s,  &g_Ah[(size_t)p * EE + c],     &g_Al[(size_t)p * EE + c]);
            bsplit(cc, &g_Ah[(size_t)p * EE + c + 1], &g_Al[(size_t)p * EE + c + 1]);
        }
    } else {
        __shared__ float tile[32][33];
        const int w = z - 4;
        const int bidx = blockIdx.x;
        if (bidx >= 24 * 24) return;
        const float* W = (w == 0) ? Wq : (w == 1) ? Wk : (w == 2) ? Wv : (w == 3) ? Wo : Wp;
        __nv_bfloat16* Th = (w == 0) ? g_WqH : (w == 1) ? g_WkH : (w == 2) ? g_WvH : (w == 3) ? g_WoH : g_WpH;
        __nv_bfloat16* Tl = (w == 0) ? g_WqL : (w == 1) ? g_WkL : (w == 2) ? g_WvL : (w == 3) ? g_WoL : g_WpL;
        int bx = (bidx % 24) * 32;
        int by = (bidx / 24) * 32;
        int x = t & 31, y0 = t >> 5;
        #pragma unroll
        for (int j = 0; j < 32; j += 8)
            tile[y0 + j][x] = W[(size_t)(by + y0 + j) * EE + bx + x];
        __syncthreads();
        #pragma unroll
        for (int j = 0; j < 32; j += 8) {
            int n = bx + y0 + j, k = by + x;
            bsplit(tile[x][y0 + j], &Th[(size_t)n * EE + k], &Tl[(size_t)n * EE + k]);
        }
    }
}

// ================= shared GEMM body (mma.sync split-bf16), 128x128 tile =================
#define GSMEM (2 * 20480 * 2)
__device__ __forceinline__ void gemm_body(
    __nv_bfloat16* sm,
    const __nv_bfloat16* __restrict__ Ah, const __nv_bfloat16* __restrict__ Al,
    const __nv_bfloat16* __restrict__ Bh, const __nv_bfloat16* __restrict__ Bl,
    const float* __restrict__ bias, float* __restrict__ C, int M, int Nn, int K,
    int mode, const float* __restrict__ rwb, const float* __restrict__ rrb,
    int bx, int by)
{
    const uint32_t sbase = smem_to_u32(sm);
    const int t = threadIdx.x;
    const int lane = t & 31, wid = t >> 5;
    const int wm = wid & 3, wn = wid >> 2;
    const int m0 = by * 128, n0c = bx * 128;
    const int g = lane >> 2, tc = lane & 3;

    const int arow = t >> 1, aq = t & 1;
    const uint32_t asz = (m0 + arow < M) ? 16u : 0u;
    const int nk = K / 32;

    float acc[2][8][4];
    #pragma unroll
    for (int a = 0; a < 2; a++)
        #pragma unroll
        for (int b = 0; b < 8; b++)
            #pragma unroll
            for (int cix = 0; cix < 4; cix++) acc[a][b][cix] = 0.f;

    auto issue = [&](int c) {
        const int st = c & 1;
        const int k0 = c * 32;
        const uint32_t soff = (uint32_t)st * 20480;
        const __nv_bfloat16* gah = Ah + (size_t)(m0 + arow) * K + k0 + aq * 16;
        const __nv_bfloat16* gal = Al + (size_t)(m0 + arow) * K + k0 + aq * 16;
        const __nv_bfloat16* gbh = Bh + (size_t)(n0c + arow) * K + k0 + aq * 16;
        const __nv_bfloat16* gbl = Bl + (size_t)(n0c + arow) * K + k0 + aq * 16;
        uint32_t da = sbase + (soff + arow * 40 + aq * 16) * 2;
        cp16(da,              gah,     asz);
        cp16(da + 16,         gah + 8, asz);
        cp16(da + 5120 * 2,       gal,     asz);
        cp16(da + 5120 * 2 + 16,  gal + 8, asz);
        cp16(da + 10240 * 2,      gbh,     16u);
        cp16(da + 10240 * 2 + 16, gbh + 8, 16u);
        cp16(da + 15360 * 2,      gbl,     16u);
        cp16(da + 15360 * 2 + 16, gbl + 8, 16u);
    };

    issue(0);
    asm volatile("cp.async.commit_group;");

    for (int c = 0; c < nk; c++) {
        if (c + 1 < nk) {
            issue(c + 1);
            asm volatile("cp.async.commit_group;");
            asm volatile("cp.async.wait_group 1;");
        } else {
            asm volatile("cp.async.wait_group 0;");
        }
        __syncthreads();
        const uint32_t s0 = (uint32_t)(c & 1) * 20480;
        #pragma unroll
        for (int ks = 0; ks < 2; ks++) {
            const int kk = ks * 16 + tc * 2;
            uint32_t fah[2][4], fal[2][4];
            #pragma unroll
            for (int mt = 0; mt < 2; mt++) {
                int r = wm * 32 + mt * 16 + g;
                fah[mt][0] = *(const uint32_t*)&sm[s0 + r * 40 + kk];
                fah[mt][1] = *(const uint32_t*)&sm[s0 + (r + 8) * 40 + kk];
                fah[mt][2] = *(const uint32_t*)&sm[s0 + r * 40 + kk + 8];
                fah[mt][3] = *(const uint32_t*)&sm[s0 + (r + 8) * 40 + kk + 8];
                fal[mt][0] = *(const uint32_t*)&sm[s0 + 5120 + r * 40 + kk];
                fal[mt][1] = *(const uint32_t*)&sm[s0 + 5120 + (r + 8) * 40 + kk];
                fal[mt][2] = *(const uint32_t*)&sm[s0 + 5120 + r * 40 + kk + 8];
                fal[mt][3] = *(const uint32_t*)&sm[s0 + 5120 + (r + 8) * 40 + kk + 8];
            }
            #pragma unroll
            for (int nt = 0; nt < 8; nt++) {
                int n = wn * 64 + nt * 8 + g;
                uint32_t fbh[2], fbl[2];
                fbh[0] = *(const uint32_t*)&sm[s0 + 10240 + n * 40 + kk];
                fbh[1] = *(const uint32_t*)&sm[s0 + 10240 + n * 40 + kk + 8];
                fbl[0] = *(const uint32_t*)&sm[s0 + 15360 + n * 40 + kk];
                fbl[1] = *(const uint32_t*)&sm[s0 + 15360 + n * 40 + kk + 8];
                #pragma unroll
                for (int mt = 0; mt < 2; mt++) {
                    mma16816(acc[mt][nt], fah[mt], fbh);
                    mma16816(acc[mt][nt], fah[mt], fbl);
                    mma16816(acc[mt][nt], fal[mt], fbh);
                }
            }
        }
        __syncthreads();
    }

    if (mode == 0) {
        #pragma unroll
        for (int mt = 0; mt < 2; mt++) {
            int r = m0 + wm * 32 + mt * 16 + g;
            #pragma unroll
            for (int nt = 0; nt < 8; nt++) {
                int cc = n0c + wn * 64 + nt * 8 + tc * 2;
                float b0 = bias[cc], b1 = bias[cc + 1];
                if (r < M) {
                    *(float2*)&C[(size_t)r * Nn + cc] =
                        make_float2(acc[mt][nt][0] + b0, acc[mt][nt][1] + b1);
                }
                if (r + 8 < M) {
                    *(float2*)&C[(size_t)(r + 8) * Nn + cc] =
                        make_float2(acc[mt][nt][2] + b0, acc[mt][nt][3] + b1);
                }
            }
        }
    } else if (mode == 3) {
        #pragma unroll
        for (int mt = 0; mt < 2; mt++) {
            int rg = m0 + wm * 32 + mt * 16 + g;
            #pragma unroll
            for (int nt = 0; nt < 8; nt++) {
                int e = n0c + wn * 64 + nt * 8 + tc * 2;
                int h = e >> 6, d = e & 63;
                float b0 = bias[e], b1 = bias[e + 1];
                #pragma unroll
                for (int half = 0; half < 2; half++) {
                    int r = rg + half * 8;
                    if (r < MPOS) {
                        size_t o = ((size_t)h * 1024 + r) * DD + d;
                        bsplit2_store(acc[mt][nt][half * 2] + b0,
                                      acc[mt][nt][half * 2 + 1] + b1,
                                      &g_Rth[o], &g_Rtl[o]);
                    }
                }
            }
        }
    } else if (mode == 4) {
        // V: transpose-split to fp16 hi/lo via smem staging -> g_vth/g_vtl [nh][d][l]
        __nv_bfloat16* stage = sm;
        const int nb = m0 >> 9;
        const int l0 = m0 & 511;
        #pragma unroll
        for (int pass = 0; pass < 2; pass++) {
            __syncthreads();
            #pragma unroll
            for (int mt = 0; mt < 2; mt++) {
                int rloc = wm * 32 + mt * 16 + g;
                #pragma unroll
                for (int nt = 0; nt < 8; nt++) {
                    int ccl = wn * 64 + nt * 8 + tc * 2;
                    float b0 = bias[n0c + ccl], b1 = bias[n0c + ccl + 1];
                    #pragma unroll
                    for (int half = 0; half < 2; half++) {
                        int rr = rloc + half * 8;
                        float v0 = acc[mt][nt][half * 2]     + b0;
                        float v1 = acc[mt][nt][half * 2 + 1] + b1;
                        __half h0 = __float2half(v0);
                        __half h1 = __float2half(v1);
                        __half2 st;
                        if (pass == 0) { st.x = h0; st.y = h1; }
                        else {
                            st.x = __float2half(v0 - __half2float(h0));
                            st.y = __float2half(v1 - __half2float(h1));
                        }
                        *(__half2*)&stage[rr * 132 + ccl] = st;
                    }
                }
            }
            __syncthreads();
            __half* dst = (pass == 0) ? g_vth : g_vtl;
            for (int idx = t; idx < 128 * 128; idx += 256) {
                int hd = idx >> 7;
                int l  = idx & 127;
                int e  = n0c + hd;
                int hh = e >> 6, d = e & 63;
                size_t o = ((size_t)(nb * HH + hh) * DD + d) * LL + l0 + l;
                dst[o] = ((const __half*)stage)[l * 132 + hd];
            }
        }
    } else {
        #pragma unroll
        for (int mt = 0; mt < 2; mt++) {
            int rg = m0 + wm * 32 + mt * 16 + g;
            #pragma unroll
            for (int nt = 0; nt < 8; nt++) {
                int e = n0c + wn * 64 + nt * 8 + tc * 2;
                int h = e >> 6, d = e & 63;
                float b0 = bias[e], b1 = bias[e + 1];
                #pragma unroll
                for (int half = 0; half < 2; half++) {
                    int r = rg + half * 8;
                    int n = r >> 9, l = r & 511;
                    size_t o = ((size_t)(n * HH + h) * LL + l) * DD + d;
                    float v0 = acc[mt][nt][half * 2]     + b0;
                    float v1 = acc[mt][nt][half * 2 + 1] + b1;
                    if (mode == 1) {
                        bsplit2_store(v0 + rwb[e], v1 + rwb[e + 1], &g_qwh[o], &g_qwl[o]);
                        bsplit2_store(v0 + rrb[e], v1 + rrb[e + 1], &g_qrh[o], &g_qrl[o]);
                    } else {
                        bsplit2_store(v0, v1, &g_khh[o], &g_khl[o]);
                    }
                }
            }
        }
    }
}

// ---- packed launch ----
__global__ __launch_bounds__(256) void gemmAll(
    const float* __restrict__ bq, const float* __restrict__ bk,
    const float* __restrict__ bv, const float* __restrict__ bpos,
    const float* __restrict__ rwb, const float* __restrict__ rrb)
{
    extern __shared__ __nv_bfloat16 sm[];
    const int z = blockIdx.z;
    if (z == 0) {
        gemm_body(sm, g_Aqh, g_Aql, g_WqH, g_WqL, bq, nullptr, MM, EE, EE, 1, rwb, rrb,
                  blockIdx.x, blockIdx.y);
    } else if (z == 1) {
        gemm_body(sm, g_Akh, g_Akl, g_WkH, g_WkL, bk, nullptr, MM, EE, EE, 2, rwb, rrb,
                  blockIdx.x, blockIdx.y);
    } else if (z == 2) {
        gemm_body(sm, g_Avh, g_Avl, g_WvH, g_WvL, bv, nullptr, MM, EE, EE, 4, rwb, rrb,
                  blockIdx.x, blockIdx.y);
    } else {
        if (blockIdx.y >= 8) return;
        gemm_body(sm, g_Ah, g_Al, g_WpH, g_WpL, bpos, nullptr, MPOS, EE, EE, 3, rwb, rrb,
                  blockIdx.x, blockIdx.y);
    }
}

__global__ __launch_bounds__(256) void gemmO(const float* __restrict__ bo, float* __restrict__ out) {
    extern __shared__ __nv_bfloat16 sm[];
    gemm_body(sm, g_Ah, g_Al, g_WoH, g_WoL, bo, out, MM, EE, EE, 0, nullptr, nullptr,
              blockIdx.x, blockIdx.y);
}

// ================= bd batched MMA (K=64), diagonal n-tiles, band epilogue =================
__global__ __launch_bounds__(256) void bmma() {
    extern __shared__ __nv_bfloat16 sm[];
    const uint32_t sbase = smem_to_u32(sm);
    const int t = threadIdx.x;
    const int lane = t & 31, wid = t >> 5;
    const int wm = wid & 3, wn = wid >> 2;
    const int z = blockIdx.z;
    const int m0 = blockIdx.y * 128;
    const int n0c = (blockIdx.y + blockIdx.x) * 128;
    const int g = lane >> 2, tc = lane & 3;

    const __nv_bfloat16* Abh = g_qrh + (size_t)z * LL * DD;
    const __nv_bfloat16* Abl = g_qrl + (size_t)z * LL * DD;
    const size_t bstr = (size_t)(z % HH) * 1024 * DD;
    const __nv_bfloat16* Bbh = g_Rth + bstr;
    const __nv_bfloat16* Bbl = g_Rtl + bstr;

    const int arow = t >> 1, aq = t & 1;

    float acc[2][8][4];
    #pragma unroll
    for (int a = 0; a < 2; a++)
        #pragma unroll
        for (int b = 0; b < 8; b++)
            #pragma unroll
            for (int cix = 0; cix < 4; cix++) acc[a][b][cix] = 0.f;

    auto issue = [&](int c) {
        const int st = c & 1;
        const int k0 = c * 32;
        const uint32_t soff = (uint32_t)st * 20480;
        const __nv_bfloat16* gah = Abh + (size_t)(m0 + arow) * DD + k0 + aq * 16;
        const __nv_bfloat16* gal = Abl + (size_t)(m0 + arow) * DD + k0 + aq * 16;
        const __nv_bfloat16* gbh = Bbh + (size_t)(n0c + arow) * DD + k0 + aq * 16;
        const __nv_bfloat16* gbl = Bbl + (size_t)(n0c + arow) * DD + k0 + aq * 16;
        uint32_t da = sbase + (soff + arow * 40 + aq * 16) * 2;
        cp16(da,              gah,     16u);
        cp16(da + 16,         gah + 8, 16u);
        cp16(da + 5120 * 2,       gal,     16u);
        cp16(da + 5120 * 2 + 16,  gal + 8, 16u);
        cp16(da + 10240 * 2,      gbh,     16u);
        cp16(da + 10240 * 2 + 16, gbh + 8, 16u);
        cp16(da + 15360 * 2,      gbl,     16u);
        cp16(da + 15360 * 2 + 16, gbl + 8, 16u);
    };

    issue(0);
    asm volatile("cp.async.commit_group;");
    for (int c = 0; c < 2; c++) {
        if (c == 0) {
            issue(1);
            asm volatile("cp.async.commit_group;");
            asm volatile("cp.async.wait_group 1;");
        } else {
            asm volatile("cp.async.wait_group 0;");
        }
        __syncthreads();
        const uint32_t s0 = (uint32_t)(c & 1) * 20480;
        #pragma unroll
        for (int ks = 0; ks < 2; ks++) {
            const int kk = ks * 16 + tc * 2;
            uint32_t fah[2][4], fal[2][4];
            #pragma unroll
            for (int mt = 0; mt < 2; mt++) {
                int r = wm * 32 + mt * 16 + g;
                fah[mt][0] = *(const uint32_t*)&sm[s0 + r * 40 + kk];
                fah[mt][1] = *(const uint32_t*)&sm[s0 + (r + 8) * 40 + kk];
                fah[mt][2] = *(const uint32_t*)&sm[s0 + r * 40 + kk + 8];
                fah[mt][3] = *(const uint32_t*)&sm[s0 + (r + 8) * 40 + kk + 8];
                fal[mt][0] = *(const uint32_t*)&sm[s0 + 5120 + r * 40 + kk];
                fal[mt][1] = *(const uint32_t*)&sm[s0 + 5120 + (r + 8) * 40 + kk];
                fal[mt][2] = *(const uint32_t*)&sm[s0 + 5120 + r * 40 + kk + 8];
                fal[mt][3] = *(const uint32_t*)&sm[s0 + 5120 + (r + 8) * 40 + kk + 8];
            }
            #pragma unroll
            for (int nt = 0; nt < 8; nt++) {
                int n = wn * 64 + nt * 8 + g;
                uint32_t fbh[2], fbl[2];
                fbh[0] = *(const uint32_t*)&sm[s0 + 10240 + n * 40 + kk];
                fbh[1] = *(const uint32_t*)&sm[s0 + 10240 + n * 40 + kk + 8];
                fbl[0] = *(const uint32_t*)&sm[s0 + 15360 + n * 40 + kk];
                fbl[1] = *(const uint32_t*)&sm[s0 + 15360 + n * 40 + kk + 8];
                #pragma unroll
                for (int mt = 0; mt < 2; mt++) {
                    mma16816(acc[mt][nt], fah[mt], fbh);
                    mma16816(acc[mt][nt], fah[mt], fbl);
                    mma16816(acc[mt][nt], fal[mt], fbh);
                }
            }
        }
        __syncthreads();
    }

    float* Cb = g_bd + (size_t)z * LL * 512;
    #pragma unroll
    for (int mt = 0; mt < 2; mt++) {
        int r = m0 + wm * 32 + mt * 16 + g;
        #pragma unroll
        for (int nt = 0; nt < 8; nt++) {
            int cc = n0c + wn * 64 + nt * 8 + tc * 2;
            #pragma unroll
            for (int half = 0; half < 2; half++) {
                int rr = r + half * 8;
                int i0 = cc - rr;
                if ((unsigned)i0 < 512u)       Cb[(size_t)rr * 512 + i0]     = acc[mt][nt][half * 2];
                if ((unsigned)(i0 + 1) < 512u) Cb[(size_t)rr * 512 + i0 + 1] = acc[mt][nt][half * 2 + 1];
            }
        }
    }
}

// ================= fused flash attention: fp16 PV path =================
#define F_QWH 0
#define F_QWL 9216
#define F_KH  18432
#define F_KL  27648
#define F_VTH 36864
#define F_VTL 45568
#define F_HALVES 54272
#define FSMEM (F_HALVES * 2)   // 108544

__global__ __launch_bounds__(256, 2) void flash_mma() {
    extern __shared__ __nv_bfloat16 sm[];
    const uint32_t sbase = smem_to_u32(sm);

    const int t = threadIdx.x;
    const int lane = t & 31, wid = t >> 5;
    const int g = lane >> 2, tc = lane & 3;
    const int z = blockIdx.y;
    const int n = z / HH, h = z % HH;
    const int q0 = blockIdx.x * 128;
    const int r0 = wid * 16 + g, r1 = r0 + 8;

    const int l7 = lane & 7;
    const uint32_t qrow = (uint32_t)(wid * 16 + l7 + ((lane >> 3) & 1) * 8);
    const uint32_t qc8  = (uint32_t)((lane >> 4) * 8);
    const uint32_t qh_b = sbase + (F_QWH + qrow * 72 + qc8) * 2;
    const uint32_t ql_b = sbase + (F_QWL + qrow * 72 + qc8) * 2;
    const uint32_t krow = (uint32_t)(((lane >> 4) * 8) + l7);
    const uint32_t kc8  = (uint32_t)(((lane >> 3) & 1) * 8);
    const uint32_t kh_b = sbase + (F_KH + krow * 72 + kc8) * 2;
    const uint32_t kl_b = sbase + (F_KL + krow * 72 + kc8) * 2;
    const uint32_t vh_b = sbase + (F_VTH + krow * 136 + kc8) * 2;
    const uint32_t vl_b = sbase + (F_VTL + krow * 136 + kc8) * 2;

    auto issueK = [&](int kt2) {
        const int k0n = kt2 * 128;
        const __nv_bfloat16* kh = g_khh + ((size_t)z * LL + k0n) * DD;
        const __nv_bfloat16* kl = g_khl + ((size_t)z * LL + k0n) * DD;
        for (int i = t; i < 128 * 8; i += 256) {
            int r = i >> 3, cu = i & 7;
            cp16(sbase + (F_KH + r * 72) * 2 + cu * 16, kh + (size_t)r * DD + cu * 8, 16u);
            cp16(sbase + (F_KL + r * 72) * 2 + cu * 16, kl + (size_t)r * DD + cu * 8, 16u);
        }
    };
    auto issueV = [&](int kt2) {
        const int k0n = kt2 * 128;
        const __half* vh = g_vth + (size_t)z * DD * LL + k0n;
        const __half* vl = g_vtl + (size_t)z * DD * LL + k0n;
        for (int i = t; i < 64 * 16; i += 256) {
            int r = i >> 4, cu = i & 15;
            cp16(sbase + (F_VTH + r * 136) * 2 + cu * 16, vh + (size_t)r * LL + cu * 8, 16u);
            cp16(sbase + (F_VTL + r * 136) * 2 + cu * 16, vl + (size_t)r * LL + cu * 8, 16u);
        }
    };

    {
        const __nv_bfloat16* qh = g_qwh + ((size_t)z * LL + q0) * DD;
        const __nv_bfloat16* ql = g_qwl + ((size_t)z * LL + q0) * DD;
        for (int i = t; i < 128 * 8; i += 256) {
            int r = i >> 3, cu = i & 7;
            cp16(sbase + (F_QWH + r * 72) * 2 + cu * 16, qh + (size_t)r * DD + cu * 8, 16u);
            cp16(sbase + (F_QWL + r * 72) * 2 + cu * 16, ql + (size_t)r * DD + cu * 8, 16u);
        }
    }
    issueK(0);
    issueV(0);
    asm volatile("cp.async.commit_group;");

    float m0 = -1e30f, m1 = -1e30f, l0 = 0.f, l1 = 0.f;
    float acc_o[8][4];
    #pragma unroll
    for (int b = 0; b < 8; b++)
        #pragma unroll
        for (int cix = 0; cix < 4; cix++) acc_o[b][cix] = 0.f;

    const float* bdb = g_bd + (size_t)z * LL * 512;
    const float* b0p = bdb + (size_t)(q0 + r0) * 512;
    const float* b1p = bdb + (size_t)(q0 + r1) * 512;

    for (int kt = 0; kt < 4; kt++) {
        const int k0 = kt * 128;

        // ---- preload bd into S accumulator ----
        float acc_s[16][4];
        #pragma unroll
        for (int nt = 0; nt < 16; nt++) {
            const int ib = 511 - k0 - (nt * 8 + tc * 2);
            acc_s[nt][0] = b0p[ib];
            acc_s[nt][1] = b0p[ib - 1];
            acc_s[nt][2] = b1p[ib];
            acc_s[nt][3] = b1p[ib - 1];
        }

        asm volatile("cp.async.wait_group 0;");
        __syncthreads();

        // ---- S = qw @ k^T + bd (full bf16 split, accuracy-critical) ----
        #pragma unroll
        for (int ks = 0; ks < 4; ks++) {
            uint32_t fah[4], fal[4];
            ldsm4(fah, qh_b + (uint32_t)(ks * 16) * 2);
            ldsm4(fal, ql_b + (uint32_t)(ks * 16) * 2);
            #pragma unroll
            for (int p = 0; p < 8; p++) {
                uint32_t bh4[4], bl4[4];
                ldsm4(bh4, kh_b + (uint32_t)(p * 16 * 72 + ks * 16) * 2);
                ldsm4(bl4, kl_b + (uint32_t)(p * 16 * 72 + ks * 16) * 2);
                mma16816(acc_s[2 * p],     fah, bh4);
                mma16816(acc_s[2 * p],     fah, bl4);
                mma16816(acc_s[2 * p],     fal, bh4);
                mma16816(acc_s[2 * p + 1], fah, bh4 + 2);
                mma16816(acc_s[2 * p + 1], fah, bl4 + 2);
                mma16816(acc_s[2 * p + 1], fal, bh4 + 2);
            }
        }

        // ---- scale + row max ----
        float mx0 = -1e30f, mx1 = -1e30f;
        #pragma unroll
        for (int nt = 0; nt < 16; nt++) {
            float s0 = acc_s[nt][0] * 0.125f;
            float s1 = acc_s[nt][1] * 0.125f;
            float s2 = acc_s[nt][2] * 0.125f;
            float s3 = acc_s[nt][3] * 0.125f;
            acc_s[nt][0] = s0; acc_s[nt][1] = s1;
            acc_s[nt][2] = s2; acc_s[nt][3] = s3;
            mx0 = fmaxf(mx0, fmaxf(s0, s1));
            mx1 = fmaxf(mx1, fmaxf(s2, s3));
        }
        mx0 = fmaxf(mx0, __shfl_xor_sync(0xffffffffu, mx0, 1));
        mx0 = fmaxf(mx0, __shfl_xor_sync(0xffffffffu, mx0, 2));
        mx1 = fmaxf(mx1, __shfl_xor_sync(0xffffffffu, mx1, 1));
        mx1 = fmaxf(mx1, __shfl_xor_sync(0xffffffffu, mx1, 2));

        __syncthreads();
        if (kt < 3) {
            issueK(kt + 1);
            asm volatile("cp.async.commit_group;");
        }

        float nm0 = fmaxf(m0, mx0), nm1 = fmaxf(m1, mx1);
        float al0 = __expf(m0 - nm0), al1 = __expf(m1 - nm1);
        m0 = nm0; m1 = nm1;
        #pragma unroll
        for (int b = 0; b < 8; b++) {
            acc_o[b][0] *= al0; acc_o[b][1] *= al0;
            acc_o[b][2] *= al1; acc_o[b][3] *= al1;
        }

        // ---- P-pack (fp16, rounded sums for exact normalization) + fp16 PV ----
        float sum0 = 0.f, sum1 = 0.f;
        #pragma unroll
        for (int kc = 0; kc < 8; kc++) {
            uint32_t fah[4];
            #pragma unroll
            for (int half = 0; half < 2; half++) {
                const int nt = 2 * kc + half;
                float p0 = __expf(acc_s[nt][0] - m0);
                float p1 = __expf(acc_s[nt][1] - m0);
                float p2 = __expf(acc_s[nt][2] - m1);
                float p3 = __expf(acc_s[nt][3] - m1);
                __half h0 = __float2half(p0), h1 = __float2half(p1);
                __half h2 = __float2half(p2), h3 = __float2half(p3);
                sum0 += __half2float(h0) + __half2float(h1);
                sum1 += __half2float(h2) + __half2float(h3);
                fah[half * 2]     = ((uint32_t)*(uint16_t*)&h1 << 16) | *(uint16_t*)&h0;
                fah[half * 2 + 1] = ((uint32_t)*(uint16_t*)&h3 << 16) | *(uint16_t*)&h2;
            }
            #pragma unroll
            for (int p4 = 0; p4 < 4; p4++) {
                uint32_t bh4[4], bl4[4];
                ldsm4(bh4, vh_b + (uint32_t)(p4 * 16 * 136 + kc * 16) * 2);
                ldsm4(bl4, vl_b + (uint32_t)(p4 * 16 * 136 + kc * 16) * 2);
                mma16816h(acc_o[2 * p4],     fah, bh4);
                mma16816h(acc_o[2 * p4],     fah, bl4);
                mma16816h(acc_o[2 * p4 + 1], fah, bh4 + 2);
                mma16816h(acc_o[2 * p4 + 1], fah, bl4 + 2);
            }
        }
        sum0 += __shfl_xor_sync(0xffffffffu, sum0, 1);
        sum0 += __shfl_xor_sync(0xffffffffu, sum0, 2);
        sum1 += __shfl_xor_sync(0xffffffffu, sum1, 1);
        sum1 += __shfl_xor_sync(0xffffffffu, sum1, 2);
        l0 = l0 * al0 + sum0;
        l1 = l1 * al1 + sum1;

        if (kt < 3) {
            __syncthreads();
            issueV(kt + 1);
            asm volatile("cp.async.commit_group;");
        }
    }

    const float inv0 = 1.f / l0, inv1 = 1.f / l1;
    #pragma unroll
    for (int nt8 = 0; nt8 < 8; nt8++) {
        const int d = nt8 * 8 + tc * 2;
        size_t o0 = ((size_t)(n * LL) + q0 + r0) * EE + h * DD + d;
        size_t o1 = ((size_t)(n * LL) + q0 + r1) * EE + h * DD + d;
        bsplit2_store(acc_o[nt8][0] * inv0, acc_o[nt8][1] * inv0, &g_Ah[o0], &g_Al[o0]);
        bsplit2_store(acc_o[nt8][2] * inv1, acc_o[nt8][3] * inv1, &g_Ah[o1], &g_Al[o1]);
    }
}

// ================= launch =================
extern "C" void kernel_launch(void* const* d_in, const int* in_sizes, int n_in,
                              void* d_out, int out_size) {
    const float* values = (const float*)d_in[0];
    const float* keys   = (const float*)d_in[1];
    const float* query  = (const float*)d_in[2];
    const float* Wq = (const float*)d_in[3];
    const float* bq = (const float*)d_in[4];
    const float* Wk = (const float*)d_in[5];
    const float* bk = (const float*)d_in[6];
    const float* Wv = (const float*)d_in[7];
    const float* bv = (const float*)d_in[8];
    const float* Wo = (const float*)d_in[9];
    const float* bo = (const float*)d_in[10];
    const float* Wpos = (const float*)d_in[11];
    const float* bpos = (const float*)d_in[12];
    const float* rwb  = (const float*)d_in[13];
    const float* rrb  = (const float*)d_in[14];
    float* out = (float*)d_out;

    static bool attr_set = false;
    if (!attr_set) {
        cudaFuncSetAttribute(gemmAll,   cudaFuncAttributeMaxDynamicSharedMemorySize, GSMEM);
        cudaFuncSetAttribute(gemmO,     cudaFuncAttributeMaxDynamicSharedMemorySize, GSMEM);
        cudaFuncSetAttribute(bmma,      cudaFuncAttributeMaxDynamicSharedMemorySize, GSMEM);
        cudaFuncSetAttribute(flash_mma, cudaFuncAttributeMaxDynamicSharedMemorySize, FSMEM);
        attr_set = true;
    }

    prepAll<<<dim3(1536, 1, 9), 256>>>(query, keys, values, Wq, Wk, Wv, Wo, Wpos);
    gemmAll<<<dim3(6, 32, 4), 256, GSMEM>>>(bq, bk, bv, bpos, rwb, rrb);
    bmma<<<dim3(5, 4, NHB), 256, GSMEM>>>();
    flash_mma<<<dim3(LL / 128, NHB), 256, FSMEM>>>();
    gemmO<<<dim3(6, 32), 256, GSMEM>>>(bo, out);
}

// round 17
// speedup vs baseline: 1.0373x; 1.0373x over previous
#include <cuda_runtime.h>
#include <cuda_bf16.h>
#include <cuda_fp16.h>
#include <math.h>
#include <stdint.h>

#define NB 8
#define LL 512
#define EE 768
#define HH 12
#define DD 64
#define MPOS 1023
#define NHB (NB * HH)   // 96
#define MM (NB * LL)    // 4096

// ================= scratch =================
__device__ float g_bd[(size_t)NHB * LL * 512];         // band: bd[q, q+i]
__device__ __nv_bfloat16 g_Ah[MM * EE];                // pe staging, later O staging
__device__ __nv_bfloat16 g_Al[MM * EE];
__device__ __nv_bfloat16 g_Aqh[MM * EE], g_Aql[MM * EE];
__device__ __nv_bfloat16 g_Akh[MM * EE], g_Akl[MM * EE];
__device__ __nv_bfloat16 g_Avh[MM * EE], g_Avl[MM * EE];
__device__ __nv_bfloat16 g_WqH[EE * EE], g_WqL[EE * EE];
__device__ __nv_bfloat16 g_WkH[EE * EE], g_WkL[EE * EE];
__device__ __nv_bfloat16 g_WvH[EE * EE], g_WvL[EE * EE];
__device__ __nv_bfloat16 g_WoH[EE * EE], g_WoL[EE * EE];
__device__ __nv_bfloat16 g_WpH[EE * EE], g_WpL[EE * EE];
__device__ __half        g_qwh[NHB * LL * DD], g_qwl[NHB * LL * DD];  // fp16 qw hi/lo
__device__ __nv_bfloat16 g_qrh[NHB * LL * DD], g_qrl[NHB * LL * DD];  // bf16 (bmma)
__device__ __half        g_khh[NHB * LL * DD];                        // fp16 k (hi only)
__device__ __half        g_vth[NHB * DD * LL], g_vtl[NHB * DD * LL];  // fp16 V hi/lo
__device__ __nv_bfloat16 g_Rth[HH * 1024 * DD], g_Rtl[HH * 1024 * DD];

// ================= helpers =================
__device__ __forceinline__ uint32_t smem_to_u32(const void* p) {
    uint32_t a;
    asm("{ .reg .u64 tmp; cvta.to.shared.u64 tmp, %1; cvt.u32.u64 %0, tmp; }" : "=r"(a) : "l"(p));
    return a;
}
__device__ __forceinline__ void cp16(uint32_t dst, const void* src, uint32_t sz) {
    asm volatile("cp.async.cg.shared.global [%0], [%1], 16, %2;"
                 :: "r"(dst), "l"(src), "r"(sz) : "memory");
}
__device__ __forceinline__ void mma16816(float* c, const uint32_t* a, const uint32_t* b) {
    asm volatile("mma.sync.aligned.m16n8k16.row.col.f32.bf16.bf16.f32 "
        "{%0,%1,%2,%3}, {%4,%5,%6,%7}, {%8,%9}, {%0,%1,%2,%3};"
        : "+f"(c[0]), "+f"(c[1]), "+f"(c[2]), "+f"(c[3])
        : "r"(a[0]), "r"(a[1]), "r"(a[2]), "r"(a[3]), "r"(b[0]), "r"(b[1]));
}
__device__ __forceinline__ void mma16816h(float* c, const uint32_t* a, const uint32_t* b) {
    asm volatile("mma.sync.aligned.m16n8k16.row.col.f32.f16.f16.f32 "
        "{%0,%1,%2,%3}, {%4,%5,%6,%7}, {%8,%9}, {%0,%1,%2,%3};"
        : "+f"(c[0]), "+f"(c[1]), "+f"(c[2]), "+f"(c[3])
        : "r"(a[0]), "r"(a[1]), "r"(a[2]), "r"(a[3]), "r"(b[0]), "r"(b[1]));
}
__device__ __forceinline__ void ldsm4(uint32_t* r, uint32_t addr) {
    asm volatile("ldmatrix.sync.aligned.m8n8.x4.shared.b16 {%0,%1,%2,%3}, [%4];"
        : "=r"(r[0]), "=r"(r[1]), "=r"(r[2]), "=r"(r[3]) : "r"(addr));
}
__device__ __forceinline__ void bsplit(float v, __nv_bfloat16* hi, __nv_bfloat16* lo) {
    __nv_bfloat16 h = __float2bfloat16(v);
    *hi = h;
    *lo = __float2bfloat16(v - __bfloat162float(h));
}
__device__ __forceinline__ void bsplit2_store(float a, float b,
                                              __nv_bfloat16* hip, __nv_bfloat16* lop) {
    __nv_bfloat16 ha = __float2bfloat16(a), hb = __float2bfloat16(b);
    __nv_bfloat16 la = __float2bfloat16(a - __bfloat162float(ha));
    __nv_bfloat16 lb = __float2bfloat16(b - __bfloat162float(hb));
    __nv_bfloat162 hv; hv.x = ha; hv.y = hb;
    __nv_bfloat162 lv; lv.x = la; lv.y = lb;
    *(__nv_bfloat162*)hip = hv;
    *(__nv_bfloat162*)lop = lv;
}
__device__ __forceinline__ void hsplit2_store(float a, float b,
                                              __half* hip, __half* lop) {
    __half ha = __float2half(a), hb = __float2half(b);
    __half2 hv; hv.x = ha; hv.y = hb;
    __half2 lv;
    lv.x = __float2half(a - __half2float(ha));
    lv.y = __float2half(b - __half2float(hb));
    *(__half2*)hip = hv;
    *(__half2*)lop = lv;
}

// ================= fused prep =================
__global__ void prepAll(const float* __restrict__ qy, const float* __restrict__ ky,
                        const float* __restrict__ vl,
                        const float* __restrict__ Wq, const float* __restrict__ Wk,
                        const float* __restrict__ Wv, const float* __restrict__ Wo,
                        const float* __restrict__ Wp) {
    const int z = blockIdx.z;
    const int t = threadIdx.x;
    if (z < 3) {
        int i = (blockIdx.x * 256 + t) * 8;
        if (i >= MM * EE) return;
        const float* src = (z == 0) ? qy : (z == 1) ? ky : vl;
        __nv_bfloat16* hi = (z == 0) ? g_Aqh : (z == 1) ? g_Akh : g_Avh;
        __nv_bfloat16* lo = (z == 0) ? g_Aql : (z == 1) ? g_Akl : g_Avl;
        float4 v0 = *(const float4*)(src + i);
        float4 v1 = *(const float4*)(src + i + 4);
        float vv[8] = {v0.x, v0.y, v0.z, v0.w, v1.x, v1.y, v1.z, v1.w};
        #pragma unroll
        for (int j = 0; j < 8; j += 2)
            bsplit2_store(vv[j], vv[j+1], &hi[i + j], &lo[i + j]);
    } else if (z == 3) {
        if (blockIdx.x == 0) {
            for (int k = t; k < HH * DD; k += 256) {
                int h = k >> 6, d = k & 63;
                size_t o = ((size_t)h * 1024 + 1023) * DD + d;
                g_Rth[o] = __float2bfloat16(0.f);
                g_Rtl[o] = __float2bfloat16(0.f);
            }
        }
        int i = (blockIdx.x * 256 + t) * 8;
        if (i >= MPOS * EE) return;
        #pragma unroll
        for (int j = 0; j < 8; j += 2) {
            int e = i + j;
            int p = e / EE, c = e % EE, m = c >> 1;
            float div = __expf((float)(2 * m) * (-9.210340371976184f / (float)EE));
            float ang = (float)p * div;
            float s, cc;
            __sincosf(ang, &s, &cc);
            bsplit(s,  &g_Ah[(size_t)p * EE + c],     &g_Al[(size_t)p * EE + c]);
            bsplit(cc, &g_Ah[(size_t)p * EE + c + 1], &g_Al[(size_t)p * EE + c + 1]);
        }
    } else {
        __shared__ float tile[32][33];
        const int w = z - 4;
        const int bidx = blockIdx.x;
        if (bidx >= 24 * 24) return;
        const float* W = (w == 0) ? Wq : (w == 1) ? Wk : (w == 2) ? Wv : (w == 3) ? Wo : Wp;
        __nv_bfloat16* Th = (w == 0) ? g_WqH : (w == 1) ? g_WkH : (w == 2) ? g_WvH : (w == 3) ? g_WoH : g_WpH;
        __nv_bfloat16* Tl = (w == 0) ? g_WqL : (w == 1) ? g_WkL : (w == 2) ? g_WvL : (w == 3) ? g_WoL : g_WpL;
        int bx = (bidx % 24) * 32;
        int by = (bidx / 24) * 32;
        int x = t & 31, y0 = t >> 5;
        #pragma unroll
        for (int j = 0; j < 32; j += 8)
            tile[y0 + j][x] = W[(size_t)(by + y0 + j) * EE + bx + x];
        __syncthreads();
        #pragma unroll
        for (int j = 0; j < 32; j += 8) {
            int n = bx + y0 + j, k = by + x;
            bsplit(tile[x][y0 + j], &Th[(size_t)n * EE + k], &Tl[(size_t)n * EE + k]);
        }
    }
}

// ================= shared GEMM body (mma.sync split-bf16), 128x128 tile =================
#define GSMEM (2 * 20480 * 2)
__device__ __forceinline__ void gemm_body(
    __nv_bfloat16* sm,
    const __nv_bfloat16* __restrict__ Ah, const __nv_bfloat16* __restrict__ Al,
    const __nv_bfloat16* __restrict__ Bh, const __nv_bfloat16* __restrict__ Bl,
    const float* __restrict__ bias, float* __restrict__ C, int M, int Nn, int K,
    int mode, const float* __restrict__ rwb, const float* __restrict__ rrb,
    int bx, int by)
{
    const uint32_t sbase = smem_to_u32(sm);
    const int t = threadIdx.x;
    const int lane = t & 31, wid = t >> 5;
    const int wm = wid & 3, wn = wid >> 2;
    const int m0 = by * 128, n0c = bx * 128;
    const int g = lane >> 2, tc = lane & 3;

    const int arow = t >> 1, aq = t & 1;
    const uint32_t asz = (m0 + arow < M) ? 16u : 0u;
    const int nk = K / 32;

    float acc[2][8][4];
    #pragma unroll
    for (int a = 0; a < 2; a++)
        #pragma unroll
        for (int b = 0; b < 8; b++)
            #pragma unroll
            for (int cix = 0; cix < 4; cix++) acc[a][b][cix] = 0.f;

    auto issue = [&](int c) {
        const int st = c & 1;
        const int k0 = c * 32;
        const uint32_t soff = (uint32_t)st * 20480;
        const __nv_bfloat16* gah = Ah + (size_t)(m0 + arow) * K + k0 + aq * 16;
        const __nv_bfloat16* gal = Al + (size_t)(m0 + arow) * K + k0 + aq * 16;
        const __nv_bfloat16* gbh = Bh + (size_t)(n0c + arow) * K + k0 + aq * 16;
        const __nv_bfloat16* gbl = Bl + (size_t)(n0c + arow) * K + k0 + aq * 16;
        uint32_t da = sbase + (soff + arow * 40 + aq * 16) * 2;
        cp16(da,              gah,     asz);
        cp16(da + 16,         gah + 8, asz);
        cp16(da + 5120 * 2,       gal,     asz);
        cp16(da + 5120 * 2 + 16,  gal + 8, asz);
        cp16(da + 10240 * 2,      gbh,     16u);
        cp16(da + 10240 * 2 + 16, gbh + 8, 16u);
        cp16(da + 15360 * 2,      gbl,     16u);
        cp16(da + 15360 * 2 + 16, gbl + 8, 16u);
    };

    issue(0);
    asm volatile("cp.async.commit_group;");

    for (int c = 0; c < nk; c++) {
        if (c + 1 < nk) {
            issue(c + 1);
            asm volatile("cp.async.commit_group;");
            asm volatile("cp.async.wait_group 1;");
        } else {
            asm volatile("cp.async.wait_group 0;");
        }
        __syncthreads();
        const uint32_t s0 = (uint32_t)(c & 1) * 20480;
        #pragma unroll
        for (int ks = 0; ks < 2; ks++) {
            const int kk = ks * 16 + tc * 2;
            uint32_t fah[2][4], fal[2][4];
            #pragma unroll
            for (int mt = 0; mt < 2; mt++) {
                int r = wm * 32 + mt * 16 + g;
                fah[mt][0] = *(const uint32_t*)&sm[s0 + r * 40 + kk];
                fah[mt][1] = *(const uint32_t*)&sm[s0 + (r + 8) * 40 + kk];
                fah[mt][2] = *(const uint32_t*)&sm[s0 + r * 40 + kk + 8];
                fah[mt][3] = *(const uint32_t*)&sm[s0 + (r + 8) * 40 + kk + 8];
                fal[mt][0] = *(const uint32_t*)&sm[s0 + 5120 + r * 40 + kk];
                fal[mt][1] = *(const uint32_t*)&sm[s0 + 5120 + (r + 8) * 40 + kk];
                fal[mt][2] = *(const uint32_t*)&sm[s0 + 5120 + r * 40 + kk + 8];
                fal[mt][3] = *(const uint32_t*)&sm[s0 + 5120 + (r + 8) * 40 + kk + 8];
            }
            #pragma unroll
            for (int nt = 0; nt < 8; nt++) {
                int n = wn * 64 + nt * 8 + g;
                uint32_t fbh[2], fbl[2];
                fbh[0] = *(const uint32_t*)&sm[s0 + 10240 + n * 40 + kk];
                fbh[1] = *(const uint32_t*)&sm[s0 + 10240 + n * 40 + kk + 8];
                fbl[0] = *(const uint32_t*)&sm[s0 + 15360 + n * 40 + kk];
                fbl[1] = *(const uint32_t*)&sm[s0 + 15360 + n * 40 + kk + 8];
                #pragma unroll
                for (int mt = 0; mt < 2; mt++) {
                    mma16816(acc[mt][nt], fah[mt], fbh);
                    mma16816(acc[mt][nt], fah[mt], fbl);
                    mma16816(acc[mt][nt], fal[mt], fbh);
                }
            }
        }
        __syncthreads();
    }

    if (mode == 0) {
        #pragma unroll
        for (int mt = 0; mt < 2; mt++) {
            int r = m0 + wm * 32 + mt * 16 + g;
            #pragma unroll
            for (int nt = 0; nt < 8; nt++) {
                int cc = n0c + wn * 64 + nt * 8 + tc * 2;
                float b0 = bias[cc], b1 = bias[cc + 1];
                if (r < M) {
                    *(float2*)&C[(size_t)r * Nn + cc] =
                        make_float2(acc[mt][nt][0] + b0, acc[mt][nt][1] + b1);
                }
                if (r + 8 < M) {
                    *(float2*)&C[(size_t)(r + 8) * Nn + cc] =
                        make_float2(acc[mt][nt][2] + b0, acc[mt][nt][3] + b1);
                }
            }
        }
    } else if (mode == 3) {
        #pragma unroll
        for (int mt = 0; mt < 2; mt++) {
            int rg = m0 + wm * 32 + mt * 16 + g;
            #pragma unroll
            for (int nt = 0; nt < 8; nt++) {
                int e = n0c + wn * 64 + nt * 8 + tc * 2;
                int h = e >> 6, d = e & 63;
                float b0 = bias[e], b1 = bias[e + 1];
                #pragma unroll
                for (int half = 0; half < 2; half++) {
                    int r = rg + half * 8;
                    if (r < MPOS) {
                        size_t o = ((size_t)h * 1024 + r) * DD + d;
                        bsplit2_store(acc[mt][nt][half * 2] + b0,
                                      acc[mt][nt][half * 2 + 1] + b1,
                                      &g_Rth[o], &g_Rtl[o]);
                    }
                }
            }
        }
    } else if (mode == 4) {
        __nv_bfloat16* stage = sm;
        const int nb = m0 >> 9;
        const int l0 = m0 & 511;
        #pragma unroll
        for (int pass = 0; pass < 2; pass++) {
            __syncthreads();
            #pragma unroll
            for (int mt = 0; mt < 2; mt++) {
                int rloc = wm * 32 + mt * 16 + g;
                #pragma unroll
                for (int nt = 0; nt < 8; nt++) {
                    int ccl = wn * 64 + nt * 8 + tc * 2;
                    float b0 = bias[n0c + ccl], b1 = bias[n0c + ccl + 1];
                    #pragma unroll
                    for (int half = 0; half < 2; half++) {
                        int rr = rloc + half * 8;
                        float v0 = acc[mt][nt][half * 2]     + b0;
                        float v1 = acc[mt][nt][half * 2 + 1] + b1;
                        __half h0 = __float2half(v0);
                        __half h1 = __float2half(v1);
                        __half2 st;
                        if (pass == 0) { st.x = h0; st.y = h1; }
                        else {
                            st.x = __float2half(v0 - __half2float(h0));
                            st.y = __float2half(v1 - __half2float(h1));
                        }
                        *(__half2*)&stage[rr * 132 + ccl] = st;
                    }
                }
            }
            __syncthreads();
            __half* dst = (pass == 0) ? g_vth : g_vtl;
            for (int idx = t; idx < 128 * 128; idx += 256) {
                int hd = idx >> 7;
                int l  = idx & 127;
                int e  = n0c + hd;
                int hh = e >> 6, d = e & 63;
                size_t o = ((size_t)(nb * HH + hh) * DD + d) * LL + l0 + l;
                dst[o] = ((const __half*)stage)[l * 132 + hd];
            }
        }
    } else {
        #pragma unroll
        for (int mt = 0; mt < 2; mt++) {
            int rg = m0 + wm * 32 + mt * 16 + g;
            #pragma unroll
            for (int nt = 0; nt < 8; nt++) {
                int e = n0c + wn * 64 + nt * 8 + tc * 2;
                int h = e >> 6, d = e & 63;
                float b0 = bias[e], b1 = bias[e + 1];
                #pragma unroll
                for (int half = 0; half < 2; half++) {
                    int r = rg + half * 8;
                    int n = r >> 9, l = r & 511;
                    size_t o = ((size_t)(n * HH + h) * LL + l) * DD + d;
                    float v0 = acc[mt][nt][half * 2]     + b0;
                    float v1 = acc[mt][nt][half * 2 + 1] + b1;
                    if (mode == 1) {
                        // qw: fp16 hi/lo (flash S);  qr: bf16 hi/lo (bmma)
                        hsplit2_store(v0 + rwb[e], v1 + rwb[e + 1], &g_qwh[o], &g_qwl[o]);
                        bsplit2_store(v0 + rrb[e], v1 + rrb[e + 1], &g_qrh[o], &g_qrl[o]);
                    } else {
                        // k: fp16 value only
                        __half2 kv;
                        kv.x = __float2half(v0);
                        kv.y = __float2half(v1);
                        *(__half2*)&g_khh[o] = kv;
                    }
                }
            }
        }
    }
}

// ---- packed launch ----
__global__ __launch_bounds__(256) void gemmAll(
    const float* __restrict__ bq, const float* __restrict__ bk,
    const float* __restrict__ bv, const float* __restrict__ bpos,
    const float* __restrict__ rwb, const float* __restrict__ rrb)
{
    extern __shared__ __nv_bfloat16 sm[];
    const int z = blockIdx.z;
    if (z == 0) {
        gemm_body(sm, g_Aqh, g_Aql, g_WqH, g_WqL, bq, nullptr, MM, EE, EE, 1, rwb, rrb,
                  blockIdx.x, blockIdx.y);
    } else if (z == 1) {
        gemm_body(sm, g_Akh, g_Akl, g_WkH, g_WkL, bk, nullptr, MM, EE, EE, 2, rwb, rrb,
                  blockIdx.x, blockIdx.y);
    } else if (z == 2) {
        gemm_body(sm, g_Avh, g_Avl, g_WvH, g_WvL, bv, nullptr, MM, EE, EE, 4, rwb, rrb,
                  blockIdx.x, blockIdx.y);
    } else {
        if (blockIdx.y >= 8) return;
        gemm_body(sm, g_Ah, g_Al, g_WpH, g_WpL, bpos, nullptr, MPOS, EE, EE, 3, rwb, rrb,
                  blockIdx.x, blockIdx.y);
    }
}

__global__ __launch_bounds__(256) void gemmO(const float* __restrict__ bo, float* __restrict__ out) {
    extern __shared__ __nv_bfloat16 sm[];
    gemm_body(sm, g_Ah, g_Al, g_WoH, g_WoL, bo, out, MM, EE, EE, 0, nullptr, nullptr,
              blockIdx.x, blockIdx.y);
}

// ================= bd batched MMA (bf16 3-term, unchanged) =================
__global__ __launch_bounds__(256) void bmma() {
    extern __shared__ __nv_bfloat16 sm[];
    const uint32_t sbase = smem_to_u32(sm);
    const int t = threadIdx.x;
    const int lane = t & 31, wid = t >> 5;
    const int wm = wid & 3, wn = wid >> 2;
    const int z = blockIdx.z;
    const int m0 = blockIdx.y * 128;
    const int n0c = (blockIdx.y + blockIdx.x) * 128;
    const int g = lane >> 2, tc = lane & 3;

    const __nv_bfloat16* Abh = g_qrh + (size_t)z * LL * DD;
    const __nv_bfloat16* Abl = g_qrl + (size_t)z * LL * DD;
    const size_t bstr = (size_t)(z % HH) * 1024 * DD;
    const __nv_bfloat16* Bbh = g_Rth + bstr;
    const __nv_bfloat16* Bbl = g_Rtl + bstr;

    const int arow = t >> 1, aq = t & 1;

    float acc[2][8][4];
    #pragma unroll
    for (int a = 0; a < 2; a++)
        #pragma unroll
        for (int b = 0; b < 8; b++)
            #pragma unroll
            for (int cix = 0; cix < 4; cix++) acc[a][b][cix] = 0.f;

    auto issue = [&](int c) {
        const int st = c & 1;
        const int k0 = c * 32;
        const uint32_t soff = (uint32_t)st * 20480;
        const __nv_bfloat16* gah = Abh + (size_t)(m0 + arow) * DD + k0 + aq * 16;
        const __nv_bfloat16* gal = Abl + (size_t)(m0 + arow) * DD + k0 + aq * 16;
        const __nv_bfloat16* gbh = Bbh + (size_t)(n0c + arow) * DD + k0 + aq * 16;
        const __nv_bfloat16* gbl = Bbl + (size_t)(n0c + arow) * DD + k0 + aq * 16;
        uint32_t da = sbase + (soff + arow * 40 + aq * 16) * 2;
        cp16(da,              gah,     16u);
        cp16(da + 16,         gah + 8, 16u);
        cp16(da + 5120 * 2,       gal,     16u);
        cp16(da + 5120 * 2 + 16,  gal + 8, 16u);
        cp16(da + 10240 * 2,      gbh,     16u);
        cp16(da + 10240 * 2 + 16, gbh + 8, 16u);
        cp16(da + 15360 * 2,      gbl,     16u);
        cp16(da + 15360 * 2 + 16, gbl + 8, 16u);
    };

    issue(0);
    asm volatile("cp.async.commit_group;");
    for (int c = 0; c < 2; c++) {
        if (c == 0) {
            issue(1);
            asm volatile("cp.async.commit_group;");
            asm volatile("cp.async.wait_group 1;");
        } else {
            asm volatile("cp.async.wait_group 0;");
        }
        __syncthreads();
        const uint32_t s0 = (uint32_t)(c & 1) * 20480;
        #pragma unroll
        for (int ks = 0; ks < 2; ks++) {
            const int kk = ks * 16 + tc * 2;
            uint32_t fah[2][4], fal[2][4];
            #pragma unroll
            for (int mt = 0; mt < 2; mt++) {
                int r = wm * 32 + mt * 16 + g;
                fah[mt][0] = *(const uint32_t*)&sm[s0 + r * 40 + kk];
                fah[mt][1] = *(const uint32_t*)&sm[s0 + (r + 8) * 40 + kk];
                fah[mt][2] = *(const uint32_t*)&sm[s0 + r * 40 + kk + 8];
                fah[mt][3] = *(const uint32_t*)&sm[s0 + (r + 8) * 40 + kk + 8];
                fal[mt][0] = *(const uint32_t*)&sm[s0 + 5120 + r * 40 + kk];
                fal[mt][1] = *(const uint32_t*)&sm[s0 + 5120 + (r + 8) * 40 + kk];
                fal[mt][2] = *(const uint32_t*)&sm[s0 + 5120 + r * 40 + kk + 8];
                fal[mt][3] = *(const uint32_t*)&sm[s0 + 5120 + (r + 8) * 40 + kk + 8];
            }
            #pragma unroll
            for (int nt = 0; nt < 8; nt++) {
                int n = wn * 64 + nt * 8 + g;
                uint32_t fbh[2], fbl[2];
                fbh[0] = *(const uint32_t*)&sm[s0 + 10240 + n * 40 + kk];
                fbh[1] = *(const uint32_t*)&sm[s0 + 10240 + n * 40 + kk + 8];
                fbl[0] = *(const uint32_t*)&sm[s0 + 15360 + n * 40 + kk];
                fbl[1] = *(const uint32_t*)&sm[s0 + 15360 + n * 40 + kk + 8];
                #pragma unroll
                for (int mt = 0; mt < 2; mt++) {
                    mma16816(acc[mt][nt], fah[mt], fbh);
                    mma16816(acc[mt][nt], fah[mt], fbl);
                    mma16816(acc[mt][nt], fal[mt], fbh);
                }
            }
        }
        __syncthreads();
    }

    float* Cb = g_bd + (size_t)z * LL * 512;
    #pragma unroll
    for (int mt = 0; mt < 2; mt++) {
        int r = m0 + wm * 32 + mt * 16 + g;
        #pragma unroll
        for (int nt = 0; nt < 8; nt++) {
            int cc = n0c + wn * 64 + nt * 8 + tc * 2;
            #pragma unroll
            for (int half = 0; half < 2; half++) {
                int rr = r + half * 8;
                int i0 = cc - rr;
                if ((unsigned)i0 < 512u)       Cb[(size_t)rr * 512 + i0]     = acc[mt][nt][half * 2];
                if ((unsigned)(i0 + 1) < 512u) Cb[(size_t)rr * 512 + i0 + 1] = acc[mt][nt][half * 2 + 1];
            }
        }
    }
}

// ================= fused flash attention: fp16 S (2-term) + fp16 PV =================
#define F_QWH 0
#define F_QWL 9216
#define F_KH  18432
#define F_VTH 27648
#define F_VTL 36352
#define F_HALVES 45056
#define FSMEM (F_HALVES * 2)   // 90112

__global__ __launch_bounds__(256, 2) void flash_mma() {
    extern __shared__ __nv_bfloat16 sm[];
    const uint32_t sbase = smem_to_u32(sm);

    const int t = threadIdx.x;
    const int lane = t & 31, wid = t >> 5;
    const int g = lane >> 2, tc = lane & 3;
    const int z = blockIdx.y;
    const int n = z / HH, h = z % HH;
    const int q0 = blockIdx.x * 128;
    const int r0 = wid * 16 + g, r1 = r0 + 8;

    const int l7 = lane & 7;
    const uint32_t qrow = (uint32_t)(wid * 16 + l7 + ((lane >> 3) & 1) * 8);
    const uint32_t qc8  = (uint32_t)((lane >> 4) * 8);
    const uint32_t qh_b = sbase + (F_QWH + qrow * 72 + qc8) * 2;
    const uint32_t ql_b = sbase + (F_QWL + qrow * 72 + qc8) * 2;
    const uint32_t krow = (uint32_t)(((lane >> 4) * 8) + l7);
    const uint32_t kc8  = (uint32_t)(((lane >> 3) & 1) * 8);
    const uint32_t kh_b = sbase + (F_KH + krow * 72 + kc8) * 2;
    const uint32_t vh_b = sbase + (F_VTH + krow * 136 + kc8) * 2;
    const uint32_t vl_b = sbase + (F_VTL + krow * 136 + kc8) * 2;

    auto issueK = [&](int kt2) {
        const int k0n = kt2 * 128;
        const __half* kh = g_khh + ((size_t)z * LL + k0n) * DD;
        for (int i = t; i < 128 * 8; i += 256) {
            int r = i >> 3, cu = i & 7;
            cp16(sbase + (F_KH + r * 72) * 2 + cu * 16, kh + (size_t)r * DD + cu * 8, 16u);
        }
    };
    auto issueV = [&](int kt2) {
        const int k0n = kt2 * 128;
        const __half* vh = g_vth + (size_t)z * DD * LL + k0n;
        const __half* vl = g_vtl + (size_t)z * DD * LL + k0n;
        for (int i = t; i < 64 * 16; i += 256) {
            int r = i >> 4, cu = i & 15;
            cp16(sbase + (F_VTH + r * 136) * 2 + cu * 16, vh + (size_t)r * LL + cu * 8, 16u);
            cp16(sbase + (F_VTL + r * 136) * 2 + cu * 16, vl + (size_t)r * LL + cu * 8, 16u);
        }
    };

    {
        const __half* qh = g_qwh + ((size_t)z * LL + q0) * DD;
        const __half* ql = g_qwl + ((size_t)z * LL + q0) * DD;
        for (int i = t; i < 128 * 8; i += 256) {
            int r = i >> 3, cu = i & 7;
            cp16(sbase + (F_QWH + r * 72) * 2 + cu * 16, qh + (size_t)r * DD + cu * 8, 16u);
            cp16(sbase + (F_QWL + r * 72) * 2 + cu * 16, ql + (size_t)r * DD + cu * 8, 16u);
        }
    }
    issueK(0);
    issueV(0);
    asm volatile("cp.async.commit_group;");

    float m0 = -1e30f, m1 = -1e30f, l0 = 0.f, l1 = 0.f;
    float acc_o[8][4];
    #pragma unroll
    for (int b = 0; b < 8; b++)
        #pragma unroll
        for (int cix = 0; cix < 4; cix++) acc_o[b][cix] = 0.f;

    const float* bdb = g_bd + (size_t)z * LL * 512;
    const float* b0p = bdb + (size_t)(q0 + r0) * 512;
    const float* b1p = bdb + (size_t)(q0 + r1) * 512;

    for (int kt = 0; kt < 4; kt++) {
        const int k0 = kt * 128;

        // ---- preload bd into S accumulator ----
        float acc_s[16][4];
        #pragma unroll
        for (int nt = 0; nt < 16; nt++) {
            const int ib = 511 - k0 - (nt * 8 + tc * 2);
            acc_s[nt][0] = b0p[ib];
            acc_s[nt][1] = b0p[ib - 1];
            acc_s[nt][2] = b1p[ib];
            acc_s[nt][3] = b1p[ib - 1];
        }

        asm volatile("cp.async.wait_group 0;");
        __syncthreads();

        // ---- S = (Qh + Ql) @ Kh^T + bd (fp16 2-term) ----
        #pragma unroll
        for (int ks = 0; ks < 4; ks++) {
            uint32_t fah[4], fal[4];
            ldsm4(fah, qh_b + (uint32_t)(ks * 16) * 2);
            ldsm4(fal, ql_b + (uint32_t)(ks * 16) * 2);
            #pragma unroll
            for (int p = 0; p < 8; p++) {
                uint32_t bh4[4];
                ldsm4(bh4, kh_b + (uint32_t)(p * 16 * 72 + ks * 16) * 2);
                mma16816h(acc_s[2 * p],     fah, bh4);
                mma16816h(acc_s[2 * p],     fal, bh4);
                mma16816h(acc_s[2 * p + 1], fah, bh4 + 2);
                mma16816h(acc_s[2 * p + 1], fal, bh4 + 2);
            }
        }

        // ---- scale + row max ----
        float mx0 = -1e30f, mx1 = -1e30f;
        #pragma unroll
        for (int nt = 0; nt < 16; nt++) {
            float s0 = acc_s[nt][0] * 0.125f;
            float s1 = acc_s[nt][1] * 0.125f;
            float s2 = acc_s[nt][2] * 0.125f;
            float s3 = acc_s[nt][3] * 0.125f;
            acc_s[nt][0] = s0; acc_s[nt][1] = s1;
            acc_s[nt][2] = s2; acc_s[nt][3] = s3;
            mx0 = fmaxf(mx0, fmaxf(s0, s1));
            mx1 = fmaxf(mx1, fmaxf(s2, s3));
        }
        mx0 = fmaxf(mx0, __shfl_xor_sync(0xffffffffu, mx0, 1));
        mx0 = fmaxf(mx0, __shfl_xor_sync(0xffffffffu, mx0, 2));
        mx1 = fmaxf(mx1, __shfl_xor_sync(0xffffffffu, mx1, 1));
        mx1 = fmaxf(mx1, __shfl_xor_sync(0xffffffffu, mx1, 2));

        __syncthreads();
        if (kt < 3) {
            issueK(kt + 1);
            asm volatile("cp.async.commit_group;");
        }

        float nm0 = fmaxf(m0, mx0), nm1 = fmaxf(m1, mx1);
        float al0 = __expf(m0 - nm0), al1 = __expf(m1 - nm1);
        m0 = nm0; m1 = nm1;
        #pragma unroll
        for (int b = 0; b < 8; b++) {
            acc_o[b][0] *= al0; acc_o[b][1] *= al0;
            acc_o[b][2] *= al1; acc_o[b][3] *= al1;
        }

        // ---- P-pack (fp16, rounded sums) + fp16 PV ----
        float sum0 = 0.f, sum1 = 0.f;
        #pragma unroll
        for (int kc = 0; kc < 8; kc++) {
            uint32_t fah[4];
            #pragma unroll
            for (int half = 0; half < 2; half++) {
                const int nt = 2 * kc + half;
                float p0 = __expf(acc_s[nt][0] - m0);
                float p1 = __expf(acc_s[nt][1] - m0);
                float p2 = __expf(acc_s[nt][2] - m1);
                float p3 = __expf(acc_s[nt][3] - m1);
                __half h0 = __float2half(p0), h1 = __float2half(p1);
                __half h2 = __float2half(p2), h3 = __float2half(p3);
                sum0 += __half2float(h0) + __half2float(h1);
                sum1 += __half2float(h2) + __half2float(h3);
                fah[half * 2]     = ((uint32_t)*(uint16_t*)&h1 << 16) | *(uint16_t*)&h0;
                fah[half * 2 + 1] = ((uint32_t)*(uint16_t*)&h3 << 16) | *(uint16_t*)&h2;
            }
            #pragma unroll
            for (int p4 = 0; p4 < 4; p4++) {
                uint32_t bh4[4], bl4[4];
                ldsm4(bh4, vh_b + (uint32_t)(p4 * 16 * 136 + kc * 16) * 2);
                ldsm4(bl4, vl_b + (uint32_t)(p4 * 16 * 136 + kc * 16) * 2);
                mma16816h(acc_o[2 * p4],     fah, bh4);
                mma16816h(acc_o[2 * p4],     fah, bl4);
                mma16816h(acc_o[2 * p4 + 1], fah, bh4 + 2);
                mma16816h(acc_o[2 * p4 + 1], fah, bl4 + 2);
            }
        }
        sum0 += __shfl_xor_sync(0xffffffffu, sum0, 1);
        sum0 += __shfl_xor_sync(0xffffffffu, sum0, 2);
        sum1 += __shfl_xor_sync(0xffffffffu, sum1, 1);
        sum1 += __shfl_xor_sync(0xffffffffu, sum1, 2);
        l0 = l0 * al0 + sum0;
        l1 = l1 * al1 + sum1;

        if (kt < 3) {
            __syncthreads();
            issueV(kt + 1);
            asm volatile("cp.async.commit_group;");
        }
    }

    const float inv0 = 1.f / l0, inv1 = 1.f / l1;
    #pragma unroll
    for (int nt8 = 0; nt8 < 8; nt8++) {
        const int d = nt8 * 8 + tc * 2;
        size_t o0 = ((size_t)(n * LL) + q0 + r0) * EE + h * DD + d;
        size_t o1 = ((size_t)(n * LL) + q0 + r1) * EE + h * DD + d;
        bsplit2_store(acc_o[nt8][0] * inv0, acc_o[nt8][1] * inv0, &g_Ah[o0], &g_Al[o0]);
        bsplit2_store(acc_o[nt8][2] * inv1, acc_o[nt8][3] * inv1, &g_Ah[o1], &g_Al[o1]);
    }
}

// ================= launch =================
extern "C" void kernel_launch(void* const* d_in, const int* in_sizes, int n_in,
                              void* d_out, int out_size) {
    const float* values = (const float*)d_in[0];
    const float* keys   = (const float*)d_in[1];
    const float* query  = (const float*)d_in[2];
    const float* Wq = (const float*)d_in[3];
    const float* bq = (const float*)d_in[4];
    const float* Wk = (const float*)d_in[5];
    const float* bk = (const float*)d_in[6];
    const float* Wv = (const float*)d_in[7];
    const float* bv = (const float*)d_in[8];
    const float* Wo = (const float*)d_in[9];
    const float* bo = (const float*)d_in[10];
    const float* Wpos = (const float*)d_in[11];
    const float* bpos = (const float*)d_in[12];
    const float* rwb  = (const float*)d_in[13];
    const float* rrb  = (const float*)d_in[14];
    float* out = (float*)d_out;

    static bool attr_set = false;
    if (!attr_set) {
        cudaFuncSetAttribute(gemmAll,   cudaFuncAttributeMaxDynamicSharedMemorySize, GSMEM);
        cudaFuncSetAttribute(gemmO,     cudaFuncAttributeMaxDynamicSharedMemorySize, GSMEM);
        cudaFuncSetAttribute(bmma,      cudaFuncAttributeMaxDynamicSharedMemorySize, GSMEM);
        cudaFuncSetAttribute(flash_mma, cudaFuncAttributeMaxDynamicSharedMemorySize, FSMEM);
        attr_set = true;
    }

    prepAll<<<dim3(1536, 1, 9), 256>>>(query, keys, values, Wq, Wk, Wv, Wo, Wpos);
    gemmAll<<<dim3(6, 32, 4), 256, GSMEM>>>(bq, bk, bv, bpos, rwb, rrb);
    bmma<<<dim3(5, 4, NHB), 256, GSMEM>>>();
    flash_mma<<<dim3(LL / 128, NHB), 256, FSMEM>>>();
    gemmO<<<dim3(6, 32), 256, GSMEM>>>(bo, out);
}